// round 10
// baseline (speedup 1.0000x reference)
#include <cuda_runtime.h>
#include <cstdint>

// X, Y: [64, 1, 512, 512] float32
// 3x3 separable window (w = outer(g,g), g = [WA, WB, WA]), SAME conv,
// crop [5:-5,5:-5] -> [64,502,502]; loss = sum_b mean_hw(sxx*syy - 2*sxy)
// Identity: sum(loss) = sum(sxx*syy) + 2*sum(mu_x*mu_y) - 2*sum_rim A(r)A(c)xy
// A = 1 interior, A(4)=A(507)=WA, A(5)=A(506)=WA+WB (rows and cols).

#define FULLMASK 0xFFFFFFFFu
#define WA  0.30780134f
#define WB  0.38439735f
#define WAB 0.69219869f   // WA + WB

#define NS       6        // smem ring stages per warp
#define DEPTH    5        // cp.async prefetch distance
#define STAGE_F  136      // floats per array per stage (128 cols + halo + pad)
#define STAGE_FT (2 * STAGE_F)   // X + Y = 272 floats per stage

__device__ float g_part[1024];
__device__ unsigned int g_cnt = 0;

struct St {
    float Vpx[4], Vpy[4], Vpxx[4], Vpyy[4];
    float Vqx[4], Vqy[4], Vqxx[4], Vqyy[4];
    float wc[5];              // xy col weights for input cols j0-1 .. j0+3
    float accPk[4], accMUk[4];  // unmasked per-column accumulators
    float accXY;
};

__device__ __forceinline__ float colW(int c) {
    if (c > 507) return 0.0f;
    if (c == 5 || c == 506) return WAB;
    if (c == 507) return WA;
    return 1.0f;
}

// finish output row (Vp + WA*h), accumulate terms, roll Vp/Vq.
// rw = xy row weight (compile-time const at all call sites in the hot loop).
__device__ __forceinline__ void vstep(const float x[6], const float y[6],
                                      St& st, float rw) {
    float q[6], r[6];
#pragma unroll
    for (int k = 0; k < 6; k++) { q[k] = x[k] * x[k]; r[k] = y[k] * y[k]; }
    float rxy =        st.wc[0] * (x[0] * y[0]);
    rxy = fmaf(st.wc[1], x[1] * y[1], rxy);
    rxy = fmaf(st.wc[2], x[2] * y[2], rxy);
    rxy = fmaf(st.wc[3], x[3] * y[3], rxy);
    rxy = fmaf(st.wc[4], x[4] * y[4], rxy);
    st.accXY = fmaf(rw, rxy, st.accXY);
#pragma unroll
    for (int k = 0; k < 4; k++) {
        float hx  = fmaf(WA, x[k], fmaf(WB, x[k+1], WA * x[k+2]));
        float hy  = fmaf(WA, y[k], fmaf(WB, y[k+1], WA * y[k+2]));
        float hxx = fmaf(WA, q[k], fmaf(WB, q[k+1], WA * q[k+2]));
        float hyy = fmaf(WA, r[k], fmaf(WB, r[k+1], WA * r[k+2]));
        float vx  = fmaf(WA, hx,  st.Vpx[k]);
        float vy  = fmaf(WA, hy,  st.Vpy[k]);
        float vxx = fmaf(WA, hxx, st.Vpxx[k]);
        float vyy = fmaf(WA, hyy, st.Vpyy[k]);
        float sxx = fmaf(-vx, vx, vxx);
        float syy = fmaf(-vy, vy, vyy);
        st.accPk[k]  = fmaf(sxx, syy, st.accPk[k]);   // mask applied at end
        st.accMUk[k] = fmaf(vx,  vy,  st.accMUk[k]);
        st.Vpx[k]  = fmaf(WB, hx,  st.Vqx[k]);   st.Vqx[k]  = WA * hx;
        st.Vpy[k]  = fmaf(WB, hy,  st.Vqy[k]);   st.Vqy[k]  = WA * hy;
        st.Vpxx[k] = fmaf(WB, hxx, st.Vqxx[k]);  st.Vqxx[k] = WA * hxx;
        st.Vpyy[k] = fmaf(WB, hyy, st.Vqyy[k]);  st.Vqyy[k] = WA * hyy;
    }
}

__global__ void __launch_bounds__(128, 6)
loss_kernel(const float* __restrict__ X, const float* __restrict__ Y,
            float* __restrict__ out) {
    const int lane = threadIdx.x & 31;
    const int wid  = threadIdx.x >> 5;
    const int unit = blockIdx.x * 4 + wid;   // 4096 warp units
    const int b = unit >> 6;                 // image
    const int s = (unit >> 4) & 3;           // col stripe (128 output cols)
    const int t = unit & 15;                 // row strip (32 output rows)

    const int r0   = 5 + 32 * t;
    const int rend = min(r0 + 32, 507);      // last input row of strip
    const bool t0 = (t == 0), tl = (t == 15);

    const int j0    = 5 + 128 * s + 4 * lane;  // first of 4 output cols
    const int cbase = 4 + 128 * s;             // smem col-0 global col

    __shared__ __align__(16) float sbuf[4 * NS * STAGE_FT];
    float* wbuf = sbuf + wid * NS * STAGE_FT;
    const uint32_t wsa = (uint32_t)__cvta_generic_to_shared(wbuf);

    St st;
    st.accXY = 0.0f;
    st.wc[0] = (j0 == 5) ? WA : 0.0f;        // input col 4 (leftmost lane only)
#pragma unroll
    for (int k = 0; k < 4; k++) {
        st.wc[k + 1] = colW(j0 + k);
        st.accPk[k] = 0.0f; st.accMUk[k] = 0.0f;
    }

    // incremental producer pointers (advance 1 row per issue)
    const float* gx = X + ((size_t)b << 18) + (size_t)(r0 - 1) * 512 + cbase + 8 * lane;
    const float* gy = Y + ((size_t)b << 18) + (size_t)(r0 - 1) * 512 + cbase + 8 * lane;
    const size_t lastx = (size_t)((X + ((size_t)b << 18)) + 507 * 512 + cbase + 8 * lane);
    const uint32_t pr = (lane < 17) ? 1u : 0u;

    // producer: copy one row (X,Y: 136 floats each) into stage sg; clamp at 507
    auto issue = [&](int sg) {
        const float* px = gx; const float* py = gy;
        if ((size_t)px > lastx) {            // clamp: re-read row 507
            size_t over = (size_t)px - lastx;
            px = (const float*)((size_t)px - over);
            py = (const float*)((size_t)py - over);
        }
        uint32_t dx = wsa + (sg * STAGE_FT + 8 * lane) * 4;
        asm volatile(
            "{\n\t.reg .pred p;\n\t"
            "setp.ne.u32 p, %0, 0;\n\t"
            "@p cp.async.cg.shared.global [%1], [%2], 16;\n\t"
            "@p cp.async.cg.shared.global [%3], [%4], 16;\n\t"
            "@p cp.async.cg.shared.global [%5], [%6], 16;\n\t"
            "@p cp.async.cg.shared.global [%7], [%8], 16;\n\t}"
            :: "r"(pr),
               "r"(dx),                    "l"(px),
               "r"(dx + 16),               "l"(px + 4),
               "r"(dx + STAGE_F * 4),      "l"(py),
               "r"(dx + STAGE_F * 4 + 16), "l"(py + 4));
        asm volatile("cp.async.commit_group;" ::: "memory");
        gx += 512; gy += 512;
    };
    // consumer: wait oldest stage, read lane's 6+6 floats
    auto fetch = [&](int sg, float x[6], float y[6]) {
        asm volatile("cp.async.wait_group %0;" :: "n"(DEPTH - 1) : "memory");
        __syncwarp();
        const float* px = wbuf + sg * STAGE_FT + 4 * lane;
        const float* py = px + STAGE_F;
        float4 xa = *(const float4*)px;  float2 xb2 = *(const float2*)(px + 4);
        float4 ya = *(const float4*)py;  float2 yb2 = *(const float2*)(py + 4);
        x[0]=xa.x; x[1]=xa.y; x[2]=xa.z; x[3]=xa.w; x[4]=xb2.x; x[5]=xb2.y;
        y[0]=ya.x; y[1]=ya.y; y[2]=ya.z; y[3]=ya.w; y[4]=yb2.x; y[5]=yb2.y;
    };

#pragma unroll
    for (int p = 0; p < DEPTH; ++p) issue(p);
    int sg = 0, nsg = DEPTH;

    float x[6], y[6];

    // ---- prime: row r0-1 seeds Vq; xy row weight A(r0-1)
    fetch(sg, x, y);
    issue(nsg % NS); ++nsg; sg = (sg + 1) % NS;
    {
        float q[6], r[6];
#pragma unroll
        for (int k = 0; k < 6; k++) { q[k] = x[k]*x[k]; r[k] = y[k]*y[k]; }
        float rxy =        st.wc[0] * (x[0] * y[0]);
        rxy = fmaf(st.wc[1], x[1] * y[1], rxy);
        rxy = fmaf(st.wc[2], x[2] * y[2], rxy);
        rxy = fmaf(st.wc[3], x[3] * y[3], rxy);
        rxy = fmaf(st.wc[4], x[4] * y[4], rxy);
        st.accXY = fmaf(t0 ? WA : 1.0f, rxy, st.accXY);
#pragma unroll
        for (int k = 0; k < 4; k++) {
            st.Vqx[k]  = WA * fmaf(WA, x[k], fmaf(WB, x[k+1], WA * x[k+2]));
            st.Vqy[k]  = WA * fmaf(WA, y[k], fmaf(WB, y[k+1], WA * y[k+2]));
            st.Vqxx[k] = WA * fmaf(WA, q[k], fmaf(WB, q[k+1], WA * q[k+2]));
            st.Vqyy[k] = WA * fmaf(WA, r[k], fmaf(WB, r[k+1], WA * r[k+2]));
        }
    }
    // ---- prime: row r0 -> Vp for output row r0; xy row weight A(r0)
    fetch(sg, x, y);
    issue(nsg % NS); ++nsg; sg = (sg + 1) % NS;
    {
        float q[6], r[6];
#pragma unroll
        for (int k = 0; k < 6; k++) { q[k] = x[k]*x[k]; r[k] = y[k]*y[k]; }
        float rxy =        st.wc[0] * (x[0] * y[0]);
        rxy = fmaf(st.wc[1], x[1] * y[1], rxy);
        rxy = fmaf(st.wc[2], x[2] * y[2], rxy);
        rxy = fmaf(st.wc[3], x[3] * y[3], rxy);
        rxy = fmaf(st.wc[4], x[4] * y[4], rxy);
        st.accXY = fmaf(t0 ? WAB : 1.0f, rxy, st.accXY);
#pragma unroll
        for (int k = 0; k < 4; k++) {
            float hx  = fmaf(WA, x[k], fmaf(WB, x[k+1], WA * x[k+2]));
            float hy  = fmaf(WA, y[k], fmaf(WB, y[k+1], WA * y[k+2]));
            float hxx = fmaf(WA, q[k], fmaf(WB, q[k+1], WA * q[k+2]));
            float hyy = fmaf(WA, r[k], fmaf(WB, r[k+1], WA * r[k+2]));
            st.Vpx[k]  = fmaf(WB, hx,  st.Vqx[k]);   st.Vqx[k]  = WA * hx;
            st.Vpy[k]  = fmaf(WB, hy,  st.Vqy[k]);   st.Vqy[k]  = WA * hy;
            st.Vpxx[k] = fmaf(WB, hxx, st.Vqxx[k]);  st.Vqxx[k] = WA * hxx;
            st.Vpyy[k] = fmaf(WB, hyy, st.Vqyy[k]);  st.Vqyy[k] = WA * hyy;
        }
    }

    // ---- main loop: rows r0+1 .. rend-2, xy row weight 1 (constant), x2 unroll
    const int nmain = rend - 2 - r0;   // 30 (interior strips) or fewer at edge
#pragma unroll 1
    for (int i = 0; i + 2 <= nmain; i += 2) {
        fetch(sg, x, y);
        issue(nsg % NS); ++nsg; sg = (sg + 1) % NS;
        vstep(x, y, st, 1.0f);
        fetch(sg, x, y);
        issue(nsg % NS); ++nsg; sg = (sg + 1) % NS;
        vstep(x, y, st, 1.0f);
    }
    if (nmain & 1) {
        fetch(sg, x, y);
        issue(nsg % NS); ++nsg; sg = (sg + 1) % NS;
        vstep(x, y, st, 1.0f);
    }
    // ---- peeled tails: rows rend-1, rend (xy rim rows owned by last strip)
    fetch(sg, x, y);
    issue(nsg % NS); sg = (sg + 1) % NS;
    vstep(x, y, st, tl ? WAB : 0.0f);        // row rend-1 (506 if tl)
    fetch(sg, x, y);
    vstep(x, y, st, tl ? WA : 0.0f);         // row rend   (507 if tl)
    asm volatile("cp.async.wait_group 0;" ::: "memory");  // drain before exit

    // apply output-col masks once, combine, reduce
    float accP = 0.0f, accMU = 0.0f;
#pragma unroll
    for (int k = 0; k < 4; k++) {
        float mk = (j0 + k <= 506) ? 1.0f : 0.0f;
        accP  = fmaf(mk, st.accPk[k],  accP);
        accMU = fmaf(mk, st.accMUk[k], accMU);
    }
    float acs = accP + 2.0f * (accMU - st.accXY);
#pragma unroll
    for (int o = 16; o > 0; o >>= 1) acs += __shfl_xor_sync(FULLMASK, acs, o);

    __shared__ float sp[4];
    __shared__ bool is_last;
    __shared__ double sh[128];
    if (lane == 0) sp[wid] = acs;
    __syncthreads();
    if (threadIdx.x == 0) {
        g_part[blockIdx.x] = (sp[0] + sp[1]) + (sp[2] + sp[3]);
        __threadfence();
        unsigned r = atomicAdd(&g_cnt, 1u);
        is_last = (r == gridDim.x - 1);
    }
    __syncthreads();
    if (is_last) {
        __threadfence();
        double ds = 0.0;
#pragma unroll
        for (int i = threadIdx.x; i < 1024; i += 128) ds += (double)g_part[i];
        sh[threadIdx.x] = ds;
        __syncthreads();
        for (int o = 64; o > 0; o >>= 1) {
            if (threadIdx.x < o) sh[threadIdx.x] += sh[threadIdx.x + o];
            __syncthreads();
        }
        if (threadIdx.x == 0) {
            out[0] = (float)(sh[0] * (1.0 / 252004.0));
            g_cnt = 0;   // reset for next graph replay (deterministic)
        }
    }
}

extern "C" void kernel_launch(void* const* d_in, const int* in_sizes, int n_in,
                              void* d_out, int out_size) {
    const float* X = (const float*)d_in[0];
    const float* Y = (const float*)d_in[1];
    float* out = (float*)d_out;

    // 4096 warps = 64 images x 4 col-stripes(128) x 16 row-strips(32); 4/block
    loss_kernel<<<1024, 128>>>(X, Y, out);
}

// round 11
// speedup vs baseline: 1.2112x; 1.2112x over previous
#include <cuda_runtime.h>
#include <cstdint>

// X, Y: [64, 1, 512, 512] float32
// 3x3 separable window (w = outer(g,g), g = [WA, WB, WA]), SAME conv,
// crop [5:-5,5:-5] -> [64,502,502]; loss = sum_b mean_hw(sxx*syy - 2*sxy)
// Identity: sum(loss) = sum(sxx*syy) + 2*sum(mu_x*mu_y) - 2*sum_rim A(r)A(c)xy
// A = 1 interior, A(4)=A(507)=WA, A(5)=A(506)=WA+WB (rows and cols).

#define FULLMASK 0xFFFFFFFFu
#define WA  0.30780134f
#define WB  0.38439735f
#define WAB 0.69219869f   // WA + WB

#define NS       6        // smem ring stages per warp
#define DEPTH    5        // cp.async prefetch distance
#define STAGE_F  136      // floats per array per stage (128 cols + halo + pad)
#define STAGE_FT (2 * STAGE_F)   // X + Y = 272 floats per stage

__device__ float g_part[1024];
__device__ unsigned int g_cnt = 0;

struct St {
    float Vpx[4], Vpy[4], Vpxx[4], Vpyy[4];
    float Vqx[4], Vqy[4], Vqxx[4], Vqyy[4];
    float wc[5];                 // xy col weights for input cols j0-1 .. j0+3
    float accPk[4], accMUk[4];   // unmasked per-column accumulators
    float accXY;
};

__device__ __forceinline__ float colW(int c) {
    if (c > 507) return 0.0f;
    if (c == 5 || c == 506) return WAB;
    if (c == 507) return WA;
    return 1.0f;
}

// finish output row (Vp + WA*h), accumulate terms, roll Vp/Vq.
// rw = xy row weight (compile-time const at hot-loop call sites).
__device__ __forceinline__ void vstep(const float x[6], const float y[6],
                                      St& st, float rw) {
    float q[6], r[6];
#pragma unroll
    for (int k = 0; k < 6; k++) { q[k] = x[k] * x[k]; r[k] = y[k] * y[k]; }
    float rxy =        st.wc[0] * (x[0] * y[0]);
    rxy = fmaf(st.wc[1], x[1] * y[1], rxy);
    rxy = fmaf(st.wc[2], x[2] * y[2], rxy);
    rxy = fmaf(st.wc[3], x[3] * y[3], rxy);
    rxy = fmaf(st.wc[4], x[4] * y[4], rxy);
    st.accXY = fmaf(rw, rxy, st.accXY);
#pragma unroll
    for (int k = 0; k < 4; k++) {
        float hx  = fmaf(WA, x[k], fmaf(WB, x[k+1], WA * x[k+2]));
        float hy  = fmaf(WA, y[k], fmaf(WB, y[k+1], WA * y[k+2]));
        float hxx = fmaf(WA, q[k], fmaf(WB, q[k+1], WA * q[k+2]));
        float hyy = fmaf(WA, r[k], fmaf(WB, r[k+1], WA * r[k+2]));
        float vx  = fmaf(WA, hx,  st.Vpx[k]);
        float vy  = fmaf(WA, hy,  st.Vpy[k]);
        float vxx = fmaf(WA, hxx, st.Vpxx[k]);
        float vyy = fmaf(WA, hyy, st.Vpyy[k]);
        float sxx = fmaf(-vx, vx, vxx);
        float syy = fmaf(-vy, vy, vyy);
        st.accPk[k]  = fmaf(sxx, syy, st.accPk[k]);   // masks applied at end
        st.accMUk[k] = fmaf(vx,  vy,  st.accMUk[k]);
        st.Vpx[k]  = fmaf(WB, hx,  st.Vqx[k]);   st.Vqx[k]  = WA * hx;
        st.Vpy[k]  = fmaf(WB, hy,  st.Vqy[k]);   st.Vqy[k]  = WA * hy;
        st.Vpxx[k] = fmaf(WB, hxx, st.Vqxx[k]);  st.Vqxx[k] = WA * hxx;
        st.Vpyy[k] = fmaf(WB, hyy, st.Vqyy[k]);  st.Vqyy[k] = WA * hyy;
    }
}

__global__ void __launch_bounds__(128, 6)
loss_kernel(const float* __restrict__ X, const float* __restrict__ Y,
            float* __restrict__ out) {
    const int lane = threadIdx.x & 31;
    const int wid  = threadIdx.x >> 5;
    const int unit = blockIdx.x * 4 + wid;   // 4096 warp units
    const int b = unit >> 6;                 // image
    const int s = (unit >> 4) & 3;           // col stripe (128 output cols)
    const int t = unit & 15;                 // row strip (32 output rows)

    const int r0   = 5 + 32 * t;
    const int rend = min(r0 + 32, 507);      // last input row of strip
    const bool t0 = (t == 0), tl = (t == 15);

    const int j0    = 5 + 128 * s + 4 * lane;  // first of 4 output cols
    const int cbase = 4 + 128 * s;             // smem col-0 global col

    const float* Xb = X + ((size_t)b << 18);
    const float* Yb = Y + ((size_t)b << 18);

    __shared__ __align__(16) float sbuf[4 * NS * STAGE_FT];
    float* wbuf = sbuf + wid * NS * STAGE_FT;
    const uint32_t wsa = (uint32_t)__cvta_generic_to_shared(wbuf);

    St st;
    st.accXY = 0.0f;
    st.wc[0] = (j0 == 5) ? WA : 0.0f;        // input col 4 (leftmost lane only)
#pragma unroll
    for (int k = 0; k < 4; k++) {
        st.wc[k + 1] = colW(j0 + k);
        st.accPk[k] = 0.0f; st.accMUk[k] = 0.0f;
    }

    // producer: copy one input row (X,Y: 136 floats each) into stage sg.
    // lanes 0..16 each copy 32B per array (2 x 16B cp.async).
    auto issue = [&](int row, int sg) {
        const float* gx = Xb + (size_t)row * 512 + cbase + 8 * lane;
        const float* gy = Yb + (size_t)row * 512 + cbase + 8 * lane;
        uint32_t dx = wsa + (sg * STAGE_FT + 8 * lane) * 4;
        asm volatile(
            "{\n\t.reg .pred p;\n\t"
            "setp.lt.u32 p, %0, 17;\n\t"
            "@p cp.async.cg.shared.global [%1], [%2], 16;\n\t"
            "@p cp.async.cg.shared.global [%3], [%4], 16;\n\t"
            "@p cp.async.cg.shared.global [%5], [%6], 16;\n\t"
            "@p cp.async.cg.shared.global [%7], [%8], 16;\n\t}"
            :: "r"((uint32_t)lane),
               "r"(dx),                       "l"(gx),
               "r"(dx + 16),                  "l"(gx + 4),
               "r"(dx + STAGE_F * 4),         "l"(gy),
               "r"(dx + STAGE_F * 4 + 16),    "l"(gy + 4));
        asm volatile("cp.async.commit_group;" ::: "memory");
    };
    // consumer: wait oldest stage, read lane's 6+6 floats
    auto fetch = [&](int sg, float x[6], float y[6]) {
        asm volatile("cp.async.wait_group %0;" :: "n"(DEPTH - 1) : "memory");
        __syncwarp();
        const float* px = wbuf + sg * STAGE_FT + 4 * lane;
        const float* py = px + STAGE_F;
        float4 xa = *(const float4*)px;  float2 xb2 = *(const float2*)(px + 4);
        float4 ya = *(const float4*)py;  float2 yb2 = *(const float2*)(py + 4);
        x[0]=xa.x; x[1]=xa.y; x[2]=xa.z; x[3]=xa.w; x[4]=xb2.x; x[5]=xb2.y;
        y[0]=ya.x; y[1]=ya.y; y[2]=ya.z; y[3]=ya.w; y[4]=yb2.x; y[5]=yb2.y;
    };

    int sg = 0;   // ring slot of next consumed row; rows consumed in order
#pragma unroll
    for (int p = 0; p < DEPTH; ++p) issue(min(r0 - 1 + p, 507), p);
    int nrow = r0 - 1 + DEPTH;   // next row to issue
    int nsg  = DEPTH;            // its slot

    float x[6], y[6];

    // ---- prime: row r0-1 seeds Vq; xy row weight A(r0-1)
    fetch(sg, x, y);
    issue(min(nrow, 507), nsg % NS);
    ++nrow; ++nsg; sg = (sg + 1) % NS;
    {
        float q[6], r[6];
#pragma unroll
        for (int k = 0; k < 6; k++) { q[k] = x[k]*x[k]; r[k] = y[k]*y[k]; }
        float rxy =        st.wc[0] * (x[0] * y[0]);
        rxy = fmaf(st.wc[1], x[1] * y[1], rxy);
        rxy = fmaf(st.wc[2], x[2] * y[2], rxy);
        rxy = fmaf(st.wc[3], x[3] * y[3], rxy);
        rxy = fmaf(st.wc[4], x[4] * y[4], rxy);
        st.accXY = fmaf(t0 ? WA : 1.0f, rxy, st.accXY);
#pragma unroll
        for (int k = 0; k < 4; k++) {
            st.Vqx[k]  = WA * fmaf(WA, x[k], fmaf(WB, x[k+1], WA * x[k+2]));
            st.Vqy[k]  = WA * fmaf(WA, y[k], fmaf(WB, y[k+1], WA * y[k+2]));
            st.Vqxx[k] = WA * fmaf(WA, q[k], fmaf(WB, q[k+1], WA * q[k+2]));
            st.Vqyy[k] = WA * fmaf(WA, r[k], fmaf(WB, r[k+1], WA * r[k+2]));
        }
    }
    // ---- prime: row r0 -> Vp for output row r0; xy row weight A(r0)
    fetch(sg, x, y);
    issue(min(nrow, 507), nsg % NS);
    ++nrow; ++nsg; sg = (sg + 1) % NS;
    {
        float q[6], r[6];
#pragma unroll
        for (int k = 0; k < 6; k++) { q[k] = x[k]*x[k]; r[k] = y[k]*y[k]; }
        float rxy =        st.wc[0] * (x[0] * y[0]);
        rxy = fmaf(st.wc[1], x[1] * y[1], rxy);
        rxy = fmaf(st.wc[2], x[2] * y[2], rxy);
        rxy = fmaf(st.wc[3], x[3] * y[3], rxy);
        rxy = fmaf(st.wc[4], x[4] * y[4], rxy);
        st.accXY = fmaf(t0 ? WAB : 1.0f, rxy, st.accXY);
#pragma unroll
        for (int k = 0; k < 4; k++) {
            float hx  = fmaf(WA, x[k], fmaf(WB, x[k+1], WA * x[k+2]));
            float hy  = fmaf(WA, y[k], fmaf(WB, y[k+1], WA * y[k+2]));
            float hxx = fmaf(WA, q[k], fmaf(WB, q[k+1], WA * q[k+2]));
            float hyy = fmaf(WA, r[k], fmaf(WB, r[k+1], WA * r[k+2]));
            st.Vpx[k]  = fmaf(WB, hx,  st.Vqx[k]);   st.Vqx[k]  = WA * hx;
            st.Vpy[k]  = fmaf(WB, hy,  st.Vqy[k]);   st.Vqy[k]  = WA * hy;
            st.Vpxx[k] = fmaf(WB, hxx, st.Vqxx[k]);  st.Vqxx[k] = WA * hxx;
            st.Vpyy[k] = fmaf(WB, hyy, st.Vqyy[k]);  st.Vqyy[k] = WA * hyy;
        }
    }

    // ---- main loop: rows r0+1 .. rend-2, xy row weight 1 (constant)
    for (int i = r0 + 1; i <= rend - 2; ++i) {
        fetch(sg, x, y);
        issue(min(nrow, 507), nsg % NS);
        ++nrow; ++nsg; sg = (sg + 1) % NS;
        vstep(x, y, st, 1.0f);
    }
    // ---- peeled tails: rows rend-1, rend (xy rim rows owned by last strip)
    fetch(sg, x, y);
    issue(min(nrow, 507), nsg % NS);
    ++nsg; sg = (sg + 1) % NS;
    vstep(x, y, st, tl ? WAB : 0.0f);        // row rend-1 (506 if tl)
    fetch(sg, x, y);
    vstep(x, y, st, tl ? WA : 0.0f);         // row rend   (507 if tl)
    asm volatile("cp.async.wait_group 0;" ::: "memory");  // drain before exit

    // apply output-col masks once, combine, reduce
    float accP = 0.0f, accMU = 0.0f;
#pragma unroll
    for (int k = 0; k < 4; k++) {
        float mk = (j0 + k <= 506) ? 1.0f : 0.0f;
        accP  = fmaf(mk, st.accPk[k],  accP);
        accMU = fmaf(mk, st.accMUk[k], accMU);
    }
    float acs = accP + 2.0f * (accMU - st.accXY);
#pragma unroll
    for (int o = 16; o > 0; o >>= 1) acs += __shfl_xor_sync(FULLMASK, acs, o);

    __shared__ float sp[4];
    __shared__ bool is_last;
    __shared__ double sh[128];
    if (lane == 0) sp[wid] = acs;
    __syncthreads();
    if (threadIdx.x == 0) {
        g_part[blockIdx.x] = (sp[0] + sp[1]) + (sp[2] + sp[3]);
        __threadfence();
        unsigned r = atomicAdd(&g_cnt, 1u);
        is_last = (r == gridDim.x - 1);
    }
    __syncthreads();
    if (is_last) {
        __threadfence();
        double ds = 0.0;
#pragma unroll
        for (int i = threadIdx.x; i < 1024; i += 128) ds += (double)g_part[i];
        sh[threadIdx.x] = ds;
        __syncthreads();
        for (int o = 64; o > 0; o >>= 1) {
            if (threadIdx.x < o) sh[threadIdx.x] += sh[threadIdx.x + o];
            __syncthreads();
        }
        if (threadIdx.x == 0) {
            out[0] = (float)(sh[0] * (1.0 / 252004.0));
            g_cnt = 0;   // reset for next graph replay (deterministic)
        }
    }
}

extern "C" void kernel_launch(void* const* d_in, const int* in_sizes, int n_in,
                              void* d_out, int out_size) {
    const float* X = (const float*)d_in[0];
    const float* Y = (const float*)d_in[1];
    float* out = (float*)d_out;

    // 4096 warps = 64 images x 4 col-stripes(128) x 16 row-strips(32); 4/block
    loss_kernel<<<1024, 128>>>(X, Y, out);
}

// round 13
// speedup vs baseline: 1.2122x; 1.0008x over previous
#include <cuda_runtime.h>
#include <cstdint>

// X, Y: [64, 1, 512, 512] float32
// 3x3 separable window (w = outer(g,g), g = [WA, WB, WA]), SAME conv,
// crop [5:-5,5:-5] -> [64,502,502]; loss = sum_b mean_hw(sxx*syy - 2*sxy)
// Identity: sum(loss) = sum(sxx*syy) + 2*sum(mu_x*mu_y) - 2*sum_rim A(r)A(c)xy
// A = 1 interior, A(4)=A(507)=WA, A(5)=A(506)=WA+WB (rows and cols), else 0.
// xy ownership: lane owns its aligned col pair (j0-1, j0) — these pairs tile
// input cols 4..515 exactly once (508..515 get weight 0).

#define FULLMASK 0xFFFFFFFFu
#define WA  0.30780134f
#define WB  0.38439735f
#define WAB 0.69219869f   // WA + WB

#define NS       8        // smem ring stages per warp
#define DEPTH    6        // cp.async prefetch distance
#define STAGE_F  68       // floats per array per stage (64 cols + halo + pad)
#define STAGE_FT (2 * STAGE_F)   // X + Y = 136 floats per stage

__device__ float g_part[1024];
__device__ unsigned int g_cnt = 0;

struct St {
    float Vpx[2], Vpy[2], Vpxx[2], Vpyy[2];
    float Vqx[2], Vqy[2], Vqxx[2], Vqyy[2];
    float w0, w1;                // xy col weights for owned cols j0-1, j0
    float accPk[2], accMUk[2];   // unmasked per-column accumulators
    float accXY;
};

__device__ __forceinline__ float colW(int c) {
    if (c < 4 || c > 507) return 0.0f;
    if (c == 4 || c == 507) return WA;      // outer rim (FIX: col 4 was 1.0)
    if (c == 5 || c == 506) return WAB;     // inner rim
    return 1.0f;
}

// finish output row (Vp + WA*h), accumulate terms, roll Vp/Vq.
// rw = xy row weight (compile-time const at hot-loop call sites).
__device__ __forceinline__ void vstep(const float x[4], const float y[4],
                                      St& st, float rw) {
    float q[4], r[4];
#pragma unroll
    for (int k = 0; k < 4; k++) { q[k] = x[k] * x[k]; r[k] = y[k] * y[k]; }
    // owned-pair xy term (cols j0-1, j0)
    float rxy = fmaf(st.w1, x[1] * y[1], st.w0 * (x[0] * y[0]));
    st.accXY = fmaf(rw, rxy, st.accXY);
#pragma unroll
    for (int k = 0; k < 2; k++) {
        float hx  = fmaf(WA, x[k], fmaf(WB, x[k+1], WA * x[k+2]));
        float hy  = fmaf(WA, y[k], fmaf(WB, y[k+1], WA * y[k+2]));
        float hxx = fmaf(WA, q[k], fmaf(WB, q[k+1], WA * q[k+2]));
        float hyy = fmaf(WA, r[k], fmaf(WB, r[k+1], WA * r[k+2]));
        float vx  = fmaf(WA, hx,  st.Vpx[k]);
        float vy  = fmaf(WA, hy,  st.Vpy[k]);
        float vxx = fmaf(WA, hxx, st.Vpxx[k]);
        float vyy = fmaf(WA, hyy, st.Vpyy[k]);
        float sxx = fmaf(-vx, vx, vxx);
        float syy = fmaf(-vy, vy, vyy);
        st.accPk[k]  = fmaf(sxx, syy, st.accPk[k]);   // masks applied at end
        st.accMUk[k] = fmaf(vx,  vy,  st.accMUk[k]);
        st.Vpx[k]  = fmaf(WB, hx,  st.Vqx[k]);   st.Vqx[k]  = WA * hx;
        st.Vpy[k]  = fmaf(WB, hy,  st.Vqy[k]);   st.Vqy[k]  = WA * hy;
        st.Vpxx[k] = fmaf(WB, hxx, st.Vqxx[k]);  st.Vqxx[k] = WA * hxx;
        st.Vpyy[k] = fmaf(WB, hyy, st.Vqyy[k]);  st.Vqyy[k] = WA * hyy;
    }
}

__global__ void __launch_bounds__(128, 8)
loss_kernel(const float* __restrict__ X, const float* __restrict__ Y,
            float* __restrict__ out) {
    const int lane = threadIdx.x & 31;
    const int wid  = threadIdx.x >> 5;
    const int unit = blockIdx.x * 4 + wid;   // 4096 warp units
    const int b = unit >> 6;                 // image
    const int s = (unit >> 3) & 7;           // col stripe (64 output cols)
    const int t = unit & 7;                  // row strip (64 output rows)

    const int r0   = 5 + 64 * t;
    const int rend = min(r0 + 64, 507);      // last input row of strip
    const bool t0 = (t == 0), tl = (t == 7);

    const int j0    = 5 + 64 * s + 2 * lane; // first of 2 output cols
    const int cbase = 4 + 64 * s;            // smem col-0 global col

    const float* Xb = X + ((size_t)b << 18);
    const float* Yb = Y + ((size_t)b << 18);

    __shared__ __align__(16) float sbuf[4 * NS * STAGE_FT];
    float* wbuf = sbuf + wid * NS * STAGE_FT;
    const uint32_t wsa = (uint32_t)__cvta_generic_to_shared(wbuf);

    St st;
    st.accXY = 0.0f;
    st.w0 = colW(j0 - 1);
    st.w1 = colW(j0);
    st.accPk[0] = st.accPk[1] = 0.0f;
    st.accMUk[0] = st.accMUk[1] = 0.0f;

    // producer: copy one input row (X,Y: 68 floats each) into stage sg.
    // lanes 0..16 each copy 16B per array.
    auto issue = [&](int row, int sg) {
        const float* gx = Xb + (size_t)row * 512 + cbase + 4 * lane;
        const float* gy = Yb + (size_t)row * 512 + cbase + 4 * lane;
        uint32_t dx = wsa + (sg * STAGE_FT + 4 * lane) * 4;
        asm volatile(
            "{\n\t.reg .pred p;\n\t"
            "setp.lt.u32 p, %0, 17;\n\t"
            "@p cp.async.cg.shared.global [%1], [%2], 16;\n\t"
            "@p cp.async.cg.shared.global [%3], [%4], 16;\n\t}"
            :: "r"((uint32_t)lane),
               "r"(dx),               "l"(gx),
               "r"(dx + STAGE_F * 4), "l"(gy));
        asm volatile("cp.async.commit_group;" ::: "memory");
    };
    // consumer: wait oldest stage, read lane's 4+4 floats
    auto fetch = [&](int sg, float x[4], float y[4]) {
        asm volatile("cp.async.wait_group %0;" :: "n"(DEPTH - 1) : "memory");
        __syncwarp();
        const float* px = wbuf + sg * STAGE_FT + 2 * lane;
        const float* py = px + STAGE_F;
        float2 xa = *(const float2*)px;  float2 xb2 = *(const float2*)(px + 2);
        float2 ya = *(const float2*)py;  float2 yb2 = *(const float2*)(py + 2);
        x[0]=xa.x; x[1]=xa.y; x[2]=xb2.x; x[3]=xb2.y;
        y[0]=ya.x; y[1]=ya.y; y[2]=yb2.x; y[3]=yb2.y;
    };

    int sg = 0;
#pragma unroll
    for (int p = 0; p < DEPTH; ++p) issue(min(r0 - 1 + p, 507), p);
    int nrow = r0 - 1 + DEPTH;
    int nsg  = DEPTH;

    float x[4], y[4];

    // ---- prime: row r0-1 seeds Vq; xy row weight A(r0-1)
    fetch(sg, x, y);
    issue(min(nrow, 507), nsg & (NS - 1));
    ++nrow; ++nsg; sg = (sg + 1) & (NS - 1);
    {
        float q[4], r[4];
#pragma unroll
        for (int k = 0; k < 4; k++) { q[k] = x[k]*x[k]; r[k] = y[k]*y[k]; }
        float rxy = fmaf(st.w1, x[1] * y[1], st.w0 * (x[0] * y[0]));
        st.accXY = fmaf(t0 ? WA : 1.0f, rxy, st.accXY);
#pragma unroll
        for (int k = 0; k < 2; k++) {
            st.Vqx[k]  = WA * fmaf(WA, x[k], fmaf(WB, x[k+1], WA * x[k+2]));
            st.Vqy[k]  = WA * fmaf(WA, y[k], fmaf(WB, y[k+1], WA * y[k+2]));
            st.Vqxx[k] = WA * fmaf(WA, q[k], fmaf(WB, q[k+1], WA * q[k+2]));
            st.Vqyy[k] = WA * fmaf(WA, r[k], fmaf(WB, r[k+1], WA * r[k+2]));
        }
    }
    // ---- prime: row r0 -> Vp for output row r0; xy row weight A(r0)
    fetch(sg, x, y);
    issue(min(nrow, 507), nsg & (NS - 1));
    ++nrow; ++nsg; sg = (sg + 1) & (NS - 1);
    {
        float q[4], r[4];
#pragma unroll
        for (int k = 0; k < 4; k++) { q[k] = x[k]*x[k]; r[k] = y[k]*y[k]; }
        float rxy = fmaf(st.w1, x[1] * y[1], st.w0 * (x[0] * y[0]));
        st.accXY = fmaf(t0 ? WAB : 1.0f, rxy, st.accXY);
#pragma unroll
        for (int k = 0; k < 2; k++) {
            float hx  = fmaf(WA, x[k], fmaf(WB, x[k+1], WA * x[k+2]));
            float hy  = fmaf(WA, y[k], fmaf(WB, y[k+1], WA * y[k+2]));
            float hxx = fmaf(WA, q[k], fmaf(WB, q[k+1], WA * q[k+2]));
            float hyy = fmaf(WA, r[k], fmaf(WB, r[k+1], WA * r[k+2]));
            st.Vpx[k]  = fmaf(WB, hx,  st.Vqx[k]);   st.Vqx[k]  = WA * hx;
            st.Vpy[k]  = fmaf(WB, hy,  st.Vqy[k]);   st.Vqy[k]  = WA * hy;
            st.Vpxx[k] = fmaf(WB, hxx, st.Vqxx[k]);  st.Vqxx[k] = WA * hxx;
            st.Vpyy[k] = fmaf(WB, hyy, st.Vqyy[k]);  st.Vqyy[k] = WA * hyy;
        }
    }

    // ---- main loop: rows r0+1 .. rend-2, xy row weight 1 (constant)
    for (int i = r0 + 1; i <= rend - 2; ++i) {
        fetch(sg, x, y);
        issue(min(nrow, 507), nsg & (NS - 1));
        ++nrow; ++nsg; sg = (sg + 1) & (NS - 1);
        vstep(x, y, st, 1.0f);
    }
    // ---- peeled tails: rows rend-1, rend (xy rim rows owned by last strip)
    fetch(sg, x, y);
    issue(min(nrow, 507), nsg & (NS - 1));
    sg = (sg + 1) & (NS - 1);
    vstep(x, y, st, tl ? WAB : 0.0f);        // row rend-1 (506 if tl)
    fetch(sg, x, y);
    vstep(x, y, st, tl ? WA : 0.0f);         // row rend   (507 if tl)
    asm volatile("cp.async.wait_group 0;" ::: "memory");  // drain before exit

    // apply output-col masks once, combine, reduce
    float mk0 = (j0     <= 506) ? 1.0f : 0.0f;
    float mk1 = (j0 + 1 <= 506) ? 1.0f : 0.0f;
    float accP  = st.accPk[0]  * mk0 + st.accPk[1]  * mk1;
    float accMU = st.accMUk[0] * mk0 + st.accMUk[1] * mk1;
    float acs = accP + 2.0f * (accMU - st.accXY);
#pragma unroll
    for (int o = 16; o > 0; o >>= 1) acs += __shfl_xor_sync(FULLMASK, acs, o);

    __shared__ float sp[4];
    __shared__ bool is_last;
    __shared__ double sh[128];
    if (lane == 0) sp[wid] = acs;
    __syncthreads();
    if (threadIdx.x == 0) {
        g_part[blockIdx.x] = (sp[0] + sp[1]) + (sp[2] + sp[3]);
        __threadfence();
        unsigned r = atomicAdd(&g_cnt, 1u);
        is_last = (r == gridDim.x - 1);
    }
    __syncthreads();
    if (is_last) {
        __threadfence();
        double ds = 0.0;
#pragma unroll
        for (int i = threadIdx.x; i < 1024; i += 128) ds += (double)g_part[i];
        sh[threadIdx.x] = ds;
        __syncthreads();
        for (int o = 64; o > 0; o >>= 1) {
            if (threadIdx.x < o) sh[threadIdx.x] += sh[threadIdx.x + o];
            __syncthreads();
        }
        if (threadIdx.x == 0) {
            out[0] = (float)(sh[0] * (1.0 / 252004.0));
            g_cnt = 0;   // reset for next graph replay (deterministic)
        }
    }
}

extern "C" void kernel_launch(void* const* d_in, const int* in_sizes, int n_in,
                              void* d_out, int out_size) {
    const float* X = (const float*)d_in[0];
    const float* Y = (const float*)d_in[1];
    float* out = (float*)d_out;

    // 4096 warps = 64 images x 8 col-stripes(64) x 8 row-strips(64); 4/block
    loss_kernel<<<1024, 128>>>(X, Y, out);
}

// round 16
// speedup vs baseline: 1.3232x; 1.0916x over previous
#include <cuda_runtime.h>
#include <cstdint>

// X, Y: [64, 1, 512, 512] float32
// 3x3 separable window (w = outer(g,g), g = [WA, WB, WA]), SAME conv,
// crop [5:-5,5:-5] -> [64,502,502]; loss = sum_b mean_hw(sxx*syy - 2*sxy)
// Identity: sum(loss) = sum(sxx*syy) + 2*sum(mu_x*mu_y) - 2*sum_rim A(r)A(c)xy
// A = 1 interior, A(4)=A(507)=WA, A(5)=A(506)=WA+WB (rows and cols), else 0.
// Block-cooperative: 4 warps = 4 col-stripes of the SAME 32-row strip; whole
// input rows staged once per block in a shared cp.async ring.
// Pipeline invariant: EVERY fetch k is preceded by exactly DEPTH+k committed
// groups, so wait_group(DEPTH-1) forces group k complete (rows clamped to 507).

#define FULLMASK 0xFFFFFFFFu
#define WA  0.30780134f
#define WB  0.38439735f
#define WAB 0.69219869f   // WA + WB

#define NS      6         // shared ring stages per block
#define DEPTH   4         // cp.async prefetch distance (rows)
#define STG_F   1024      // floats per stage: X row (512) + Y row (512)

__device__ float g_part[1024];
__device__ unsigned int g_cnt = 0;

struct St {
    float Vpx[4], Vpy[4], Vpxx[4], Vpyy[4];
    float Vqx[4], Vqy[4], Vqxx[4], Vqyy[4];
    float wc[5];                 // xy col weights for input cols j0-1 .. j0+3
    float accPk[4], accMUk[4];   // unmasked per-column accumulators
    float accXY;
};

__device__ __forceinline__ float colW(int c) {
    if (c < 4 || c > 507) return 0.0f;
    if (c == 4 || c == 507) return WA;
    if (c == 5 || c == 506) return WAB;
    return 1.0f;
}

// finish output row (Vp + WA*h), accumulate terms, roll Vp/Vq.
__device__ __forceinline__ void vstep(const float x[6], const float y[6],
                                      St& st, float rw) {
    float q[6], r[6];
#pragma unroll
    for (int k = 0; k < 6; k++) { q[k] = x[k] * x[k]; r[k] = y[k] * y[k]; }
    float rxy =        st.wc[0] * (x[0] * y[0]);
    rxy = fmaf(st.wc[1], x[1] * y[1], rxy);
    rxy = fmaf(st.wc[2], x[2] * y[2], rxy);
    rxy = fmaf(st.wc[3], x[3] * y[3], rxy);
    rxy = fmaf(st.wc[4], x[4] * y[4], rxy);
    st.accXY = fmaf(rw, rxy, st.accXY);
#pragma unroll
    for (int k = 0; k < 4; k++) {
        float hx  = fmaf(WA, x[k], fmaf(WB, x[k+1], WA * x[k+2]));
        float hy  = fmaf(WA, y[k], fmaf(WB, y[k+1], WA * y[k+2]));
        float hxx = fmaf(WA, q[k], fmaf(WB, q[k+1], WA * q[k+2]));
        float hyy = fmaf(WA, r[k], fmaf(WB, r[k+1], WA * r[k+2]));
        float vx  = fmaf(WA, hx,  st.Vpx[k]);
        float vy  = fmaf(WA, hy,  st.Vpy[k]);
        float vxx = fmaf(WA, hxx, st.Vpxx[k]);
        float vyy = fmaf(WA, hyy, st.Vpyy[k]);
        float sxx = fmaf(-vx, vx, vxx);
        float syy = fmaf(-vy, vy, vyy);
        st.accPk[k]  = fmaf(sxx, syy, st.accPk[k]);   // masks applied at end
        st.accMUk[k] = fmaf(vx,  vy,  st.accMUk[k]);
        st.Vpx[k]  = fmaf(WB, hx,  st.Vqx[k]);   st.Vqx[k]  = WA * hx;
        st.Vpy[k]  = fmaf(WB, hy,  st.Vqy[k]);   st.Vqy[k]  = WA * hy;
        st.Vpxx[k] = fmaf(WB, hxx, st.Vqxx[k]);  st.Vqxx[k] = WA * hxx;
        st.Vpyy[k] = fmaf(WB, hyy, st.Vqyy[k]);  st.Vqyy[k] = WA * hyy;
    }
}

__global__ void __launch_bounds__(128, 6)
loss_kernel(const float* __restrict__ X, const float* __restrict__ Y,
            float* __restrict__ out) {
    const int tid  = threadIdx.x;
    const int lane = tid & 31;
    const int wid  = tid >> 5;               // = col stripe s (0..3)
    const int blk  = blockIdx.x;             // 1024 = 64 images x 16 strips
    const int b    = blk >> 4;               // image
    const int t    = blk & 15;               // row strip (32 output rows)

    const int r0   = 5 + 32 * t;
    const int rend = min(r0 + 32, 507);      // last input row of strip
    const bool t0 = (t == 0), tl = (t == 15);

    const int j0 = 5 + 128 * wid + 4 * lane; // first of 4 output cols

    __shared__ __align__(16) float ring[NS * STG_F];
    __shared__ float sp[4];
    __shared__ bool is_last;
    __shared__ double sh[128];

    // producer mapping: tid 0..63 -> X row (32B each), 64..127 -> Y row
    const float* gb = ((tid < 64) ? X : Y) + ((size_t)b << 18) + (size_t)(tid & 63) * 8;
    const uint32_t dxb = (uint32_t)__cvta_generic_to_shared(ring)
                       + ((uint32_t)(tid & 63) * 8 + (uint32_t)(tid >> 6) * 512) * 4;

    St st;
    st.accXY = 0.0f;
    st.wc[0] = (j0 == 5) ? WA : 0.0f;        // input col 4 (leftmost lane, s=0)
#pragma unroll
    for (int k = 0; k < 4; k++) {
        st.wc[k + 1] = colW(j0 + k);
        st.accPk[k] = 0.0f; st.accMUk[k] = 0.0f;
    }

    // issue one whole input row into ring slot sg (all 128 threads, 32B each)
    auto issue = [&](int row, int sg) {
        const float* g = gb + (size_t)row * 512;
        uint32_t dx = dxb + (uint32_t)sg * (STG_F * 4);
        asm volatile(
            "cp.async.cg.shared.global [%0], [%1], 16;\n\t"
            "cp.async.cg.shared.global [%2], [%3], 16;"
            :: "r"(dx), "l"(g), "r"(dx + 16), "l"(g + 4));
        asm volatile("cp.async.commit_group;" ::: "memory");
    };
    // consumer: wait own groups, barrier, read lane's 6+6 floats from slot sg
    const int coff = 4 + 128 * wid + 4 * lane;   // input col j0-1 (16B aligned)
    auto fetch = [&](int sg, float x[6], float y[6]) {
        asm volatile("cp.async.wait_group %0;" :: "n"(DEPTH - 1) : "memory");
        __syncthreads();
        const float* px = ring + sg * STG_F + coff;
        const float* py = px + 512;
        float4 xa = *(const float4*)px;  float2 xb2 = *(const float2*)(px + 4);
        float4 ya = *(const float4*)py;  float2 yb2 = *(const float2*)(py + 4);
        x[0]=xa.x; x[1]=xa.y; x[2]=xa.z; x[3]=xa.w; x[4]=xb2.x; x[5]=xb2.y;
        y[0]=ya.x; y[1]=ya.y; y[2]=ya.z; y[3]=ya.w; y[4]=yb2.x; y[5]=yb2.y;
    };

    // prologue: rows r0-1 .. r0+DEPTH-2 (all <= 507, no clamp needed)
#pragma unroll
    for (int p = 0; p < DEPTH; ++p) issue(r0 - 1 + p, p);
    int sg = 0, nsg = DEPTH, nrow = r0 - 1 + DEPTH;

    float x[6], y[6];

    // ---- prime: row r0-1 seeds Vq; xy row weight A(r0-1)
    fetch(sg, x, y);
    issue(min(nrow, 507), nsg);   // unconditional: keeps wait_group accounting
    ++nrow; nsg = (nsg + 1 == NS) ? 0 : nsg + 1; sg = (sg + 1 == NS) ? 0 : sg + 1;
    {
        float q[6], r[6];
#pragma unroll
        for (int k = 0; k < 6; k++) { q[k] = x[k]*x[k]; r[k] = y[k]*y[k]; }
        float rxy =        st.wc[0] * (x[0] * y[0]);
        rxy = fmaf(st.wc[1], x[1] * y[1], rxy);
        rxy = fmaf(st.wc[2], x[2] * y[2], rxy);
        rxy = fmaf(st.wc[3], x[3] * y[3], rxy);
        rxy = fmaf(st.wc[4], x[4] * y[4], rxy);
        st.accXY = fmaf(t0 ? WA : 1.0f, rxy, st.accXY);
#pragma unroll
        for (int k = 0; k < 4; k++) {
            st.Vqx[k]  = WA * fmaf(WA, x[k], fmaf(WB, x[k+1], WA * x[k+2]));
            st.Vqy[k]  = WA * fmaf(WA, y[k], fmaf(WB, y[k+1], WA * y[k+2]));
            st.Vqxx[k] = WA * fmaf(WA, q[k], fmaf(WB, q[k+1], WA * q[k+2]));
            st.Vqyy[k] = WA * fmaf(WA, r[k], fmaf(WB, r[k+1], WA * r[k+2]));
        }
    }
    // ---- prime: row r0 -> Vp; xy row weight A(r0)
    fetch(sg, x, y);
    issue(min(nrow, 507), nsg);
    ++nrow; nsg = (nsg + 1 == NS) ? 0 : nsg + 1; sg = (sg + 1 == NS) ? 0 : sg + 1;
    {
        float q[6], r[6];
#pragma unroll
        for (int k = 0; k < 6; k++) { q[k] = x[k]*x[k]; r[k] = y[k]*y[k]; }
        float rxy =        st.wc[0] * (x[0] * y[0]);
        rxy = fmaf(st.wc[1], x[1] * y[1], rxy);
        rxy = fmaf(st.wc[2], x[2] * y[2], rxy);
        rxy = fmaf(st.wc[3], x[3] * y[3], rxy);
        rxy = fmaf(st.wc[4], x[4] * y[4], rxy);
        st.accXY = fmaf(t0 ? WAB : 1.0f, rxy, st.accXY);
#pragma unroll
        for (int k = 0; k < 4; k++) {
            float hx  = fmaf(WA, x[k], fmaf(WB, x[k+1], WA * x[k+2]));
            float hy  = fmaf(WA, y[k], fmaf(WB, y[k+1], WA * y[k+2]));
            float hxx = fmaf(WA, q[k], fmaf(WB, q[k+1], WA * q[k+2]));
            float hyy = fmaf(WA, r[k], fmaf(WB, r[k+1], WA * r[k+2]));
            st.Vpx[k]  = fmaf(WB, hx,  st.Vqx[k]);   st.Vqx[k]  = WA * hx;
            st.Vpy[k]  = fmaf(WB, hy,  st.Vqy[k]);   st.Vqy[k]  = WA * hy;
            st.Vpxx[k] = fmaf(WB, hxx, st.Vqxx[k]);  st.Vqxx[k] = WA * hxx;
            st.Vpyy[k] = fmaf(WB, hyy, st.Vqyy[k]);  st.Vqyy[k] = WA * hyy;
        }
    }

    // ---- main loop: rows r0+1 .. rend-2, xy row weight 1 (constant)
    for (int i = r0 + 1; i <= rend - 2; ++i) {
        fetch(sg, x, y);
        issue(min(nrow, 507), nsg);
        ++nrow; nsg = (nsg + 1 == NS) ? 0 : nsg + 1; sg = (sg + 1 == NS) ? 0 : sg + 1;
        vstep(x, y, st, 1.0f);
    }
    // ---- peeled tails: rows rend-1, rend (xy rim rows owned by last strip)
    fetch(sg, x, y);
    issue(min(nrow, 507), nsg);   // keeps invariant for the final fetch
    sg = (sg + 1 == NS) ? 0 : sg + 1;
    vstep(x, y, st, tl ? WAB : 0.0f);        // row rend-1 (506 if tl)
    fetch(sg, x, y);
    vstep(x, y, st, tl ? WA : 0.0f);         // row rend   (507 if tl)
    asm volatile("cp.async.wait_group 0;" ::: "memory");  // drain before exit
    __syncthreads();

    // apply output-col masks once, combine, reduce
    float accP = 0.0f, accMU = 0.0f;
#pragma unroll
    for (int k = 0; k < 4; k++) {
        float mk = (j0 + k <= 506) ? 1.0f : 0.0f;
        accP  = fmaf(mk, st.accPk[k],  accP);
        accMU = fmaf(mk, st.accMUk[k], accMU);
    }
    float acs = accP + 2.0f * (accMU - st.accXY);
#pragma unroll
    for (int o = 16; o > 0; o >>= 1) acs += __shfl_xor_sync(FULLMASK, acs, o);

    if (lane == 0) sp[wid] = acs;
    __syncthreads();
    if (tid == 0) {
        g_part[blk] = (sp[0] + sp[1]) + (sp[2] + sp[3]);
        __threadfence();
        unsigned r = atomicAdd(&g_cnt, 1u);
        is_last = (r == gridDim.x - 1);
    }
    __syncthreads();
    if (is_last) {
        __threadfence();
        double ds = 0.0;
#pragma unroll
        for (int i = tid; i < 1024; i += 128) ds += (double)g_part[i];
        sh[tid] = ds;
        __syncthreads();
        for (int o = 64; o > 0; o >>= 1) {
            if (tid < o) sh[tid] += sh[tid + o];
            __syncthreads();
        }
        if (tid == 0) {
            out[0] = (float)(sh[0] * (1.0 / 252004.0));
            g_cnt = 0;   // reset for next graph replay (deterministic)
        }
    }
}

extern "C" void kernel_launch(void* const* d_in, const int* in_sizes, int n_in,
                              void* d_out, int out_size) {
    const float* X = (const float*)d_in[0];
    const float* Y = (const float*)d_in[1];
    float* out = (float*)d_out;

    // 1024 blocks = 64 images x 16 row-strips(32); 4 warps = 4 col-stripes(128)
    loss_kernel<<<1024, 128>>>(X, Y, out);
}

// round 17
// speedup vs baseline: 1.4325x; 1.0826x over previous
#include <cuda_runtime.h>
#include <cstdint>

// X, Y: [64, 1, 512, 512] float32
// 3x3 separable window (w = outer(g,g), g = [WA, WB, WA]), SAME conv,
// crop [5:-5,5:-5] -> [64,502,502]; loss = sum_b mean_hw(sxx*syy - 2*sxy)
// Identity: sum(loss) = sum(sxx*syy) + 2*sum(mu_x*mu_y) - 2*sum_rim A(r)A(c)xy
// A = 1 interior, A(4)=A(507)=WA, A(5)=A(506)=WA+WB (rows and cols), else 0.
// Block-cooperative: 4 warps = 4 col-stripes of the SAME 32-row strip; whole
// input rows staged once per block in a shared cp.async ring.
// Pipeline invariant: EVERY fetch k is preceded by exactly DEPTH+k committed
// groups, so wait_group(DEPTH-1) forces group k complete (rows clamped to 507).

#define FULLMASK 0xFFFFFFFFu
#define WA  0.30780134f
#define WB  0.38439735f
#define WAB 0.69219869f   // WA + WB

#define NS      6         // shared ring stages per block
#define DEPTH   4         // cp.async prefetch distance (rows)
#define STG_F   1024      // floats per stage: X row (512) + Y row (512)

__device__ float g_part[1024];
__device__ unsigned int g_cnt = 0;

struct St {
    float Vpx[4], Vpy[4], Vpxx[4], Vpyy[4];
    float Vqx[4], Vqy[4], Vqxx[4], Vqyy[4];
    float wc[5];      // xy col weights for input cols j0-1 .. j0+3
    float accC[4];    // unmasked per-column accumulators: sxx*syy + 2*vx*vy
    float accXY;
};

__device__ __forceinline__ float colW(int c) {
    if (c < 4 || c > 507) return 0.0f;
    if (c == 4 || c == 507) return WA;
    if (c == 5 || c == 506) return WAB;
    return 1.0f;
}

// finish output row (Vp + WA*h), accumulate terms, roll Vp/Vq.
__device__ __forceinline__ void vstep(const float x[6], const float y[6],
                                      St& st, float rw) {
    float q[6], r[6];
#pragma unroll
    for (int k = 0; k < 6; k++) { q[k] = x[k] * x[k]; r[k] = y[k] * y[k]; }
    float rxy =        st.wc[0] * (x[0] * y[0]);
    rxy = fmaf(st.wc[1], x[1] * y[1], rxy);
    rxy = fmaf(st.wc[2], x[2] * y[2], rxy);
    rxy = fmaf(st.wc[3], x[3] * y[3], rxy);
    rxy = fmaf(st.wc[4], x[4] * y[4], rxy);
    st.accXY = fmaf(rw, rxy, st.accXY);
#pragma unroll
    for (int k = 0; k < 4; k++) {
        float hx  = fmaf(WA, x[k], fmaf(WB, x[k+1], WA * x[k+2]));
        float hy  = fmaf(WA, y[k], fmaf(WB, y[k+1], WA * y[k+2]));
        float hxx = fmaf(WA, q[k], fmaf(WB, q[k+1], WA * q[k+2]));
        float hyy = fmaf(WA, r[k], fmaf(WB, r[k+1], WA * r[k+2]));
        float vx  = fmaf(WA, hx,  st.Vpx[k]);
        float vy  = fmaf(WA, hy,  st.Vpy[k]);
        float vxx = fmaf(WA, hxx, st.Vpxx[k]);
        float vyy = fmaf(WA, hyy, st.Vpyy[k]);
        float sxx = fmaf(-vx, vx, vxx);
        float syy = fmaf(-vy, vy, vyy);
        float vx2 = vx + vx;
        st.accC[k] = fmaf(sxx, syy, fmaf(vx2, vy, st.accC[k]));  // masks at end
        st.Vpx[k]  = fmaf(WB, hx,  st.Vqx[k]);   st.Vqx[k]  = WA * hx;
        st.Vpy[k]  = fmaf(WB, hy,  st.Vqy[k]);   st.Vqy[k]  = WA * hy;
        st.Vpxx[k] = fmaf(WB, hxx, st.Vqxx[k]);  st.Vqxx[k] = WA * hxx;
        st.Vpyy[k] = fmaf(WB, hyy, st.Vqyy[k]);  st.Vqyy[k] = WA * hyy;
    }
}

__global__ void __launch_bounds__(128, 7)
loss_kernel(const float* __restrict__ X, const float* __restrict__ Y,
            float* __restrict__ out) {
    const int tid  = threadIdx.x;
    const int lane = tid & 31;
    const int wid  = tid >> 5;               // = col stripe s (0..3)
    const int blk  = blockIdx.x;             // 1024 = 64 images x 16 strips
    const int b    = blk >> 4;               // image
    const int t    = blk & 15;               // row strip (32 output rows)

    const int r0   = 5 + 32 * t;
    const int rend = min(r0 + 32, 507);      // last input row of strip
    const bool t0 = (t == 0), tl = (t == 15);

    const int j0 = 5 + 128 * wid + 4 * lane; // first of 4 output cols

    __shared__ __align__(16) float ring[NS * STG_F];
    __shared__ float sp[4];
    __shared__ bool is_last;
    __shared__ double sh[128];

    // producer mapping: tid 0..63 -> X row (32B each), 64..127 -> Y row
    const float* gb = ((tid < 64) ? X : Y) + ((size_t)b << 18) + (size_t)(tid & 63) * 8;
    const uint32_t dxb = (uint32_t)__cvta_generic_to_shared(ring)
                       + ((uint32_t)(tid & 63) * 8 + (uint32_t)(tid >> 6) * 512) * 4;

    St st;
    st.accXY = 0.0f;
    st.wc[0] = (j0 == 5) ? WA : 0.0f;        // input col 4 (leftmost lane, s=0)
#pragma unroll
    for (int k = 0; k < 4; k++) {
        st.wc[k + 1] = colW(j0 + k);
        st.accC[k] = 0.0f;
    }

    // issue one whole input row into ring slot sg (all 128 threads, 32B each)
    auto issue = [&](int row, int sg) {
        const float* g = gb + (size_t)row * 512;
        uint32_t dx = dxb + (uint32_t)sg * (STG_F * 4);
        asm volatile(
            "cp.async.cg.shared.global [%0], [%1], 16;\n\t"
            "cp.async.cg.shared.global [%2], [%3], 16;"
            :: "r"(dx), "l"(g), "r"(dx + 16), "l"(g + 4));
        asm volatile("cp.async.commit_group;" ::: "memory");
    };
    // consumer: wait own groups, barrier, read lane's 6+6 floats from slot sg
    const int coff = 4 + 128 * wid + 4 * lane;   // input col j0-1 (16B aligned)
    auto fetch = [&](int sg, float x[6], float y[6]) {
        asm volatile("cp.async.wait_group %0;" :: "n"(DEPTH - 1) : "memory");
        __syncthreads();
        const float* px = ring + sg * STG_F + coff;
        const float* py = px + 512;
        float4 xa = *(const float4*)px;  float2 xb2 = *(const float2*)(px + 4);
        float4 ya = *(const float4*)py;  float2 yb2 = *(const float2*)(py + 4);
        x[0]=xa.x; x[1]=xa.y; x[2]=xa.z; x[3]=xa.w; x[4]=xb2.x; x[5]=xb2.y;
        y[0]=ya.x; y[1]=ya.y; y[2]=ya.z; y[3]=ya.w; y[4]=yb2.x; y[5]=yb2.y;
    };

    // prologue: rows r0-1 .. r0+DEPTH-2 (all <= 507, no clamp needed)
#pragma unroll
    for (int p = 0; p < DEPTH; ++p) issue(r0 - 1 + p, p);
    int sg = 0, nsg = DEPTH, nrow = r0 - 1 + DEPTH;

    float x[6], y[6];

    // ---- prime: row r0-1 seeds Vq; xy row weight A(r0-1)
    fetch(sg, x, y);
    issue(min(nrow, 507), nsg);   // unconditional: keeps wait_group accounting
    ++nrow; nsg = (nsg + 1 == NS) ? 0 : nsg + 1; sg = (sg + 1 == NS) ? 0 : sg + 1;
    {
        float q[6], r[6];
#pragma unroll
        for (int k = 0; k < 6; k++) { q[k] = x[k]*x[k]; r[k] = y[k]*y[k]; }
        float rxy =        st.wc[0] * (x[0] * y[0]);
        rxy = fmaf(st.wc[1], x[1] * y[1], rxy);
        rxy = fmaf(st.wc[2], x[2] * y[2], rxy);
        rxy = fmaf(st.wc[3], x[3] * y[3], rxy);
        rxy = fmaf(st.wc[4], x[4] * y[4], rxy);
        st.accXY = fmaf(t0 ? WA : 1.0f, rxy, st.accXY);
#pragma unroll
        for (int k = 0; k < 4; k++) {
            st.Vqx[k]  = WA * fmaf(WA, x[k], fmaf(WB, x[k+1], WA * x[k+2]));
            st.Vqy[k]  = WA * fmaf(WA, y[k], fmaf(WB, y[k+1], WA * y[k+2]));
            st.Vqxx[k] = WA * fmaf(WA, q[k], fmaf(WB, q[k+1], WA * q[k+2]));
            st.Vqyy[k] = WA * fmaf(WA, r[k], fmaf(WB, r[k+1], WA * r[k+2]));
        }
    }
    // ---- prime: row r0 -> Vp; xy row weight A(r0)
    fetch(sg, x, y);
    issue(min(nrow, 507), nsg);
    ++nrow; nsg = (nsg + 1 == NS) ? 0 : nsg + 1; sg = (sg + 1 == NS) ? 0 : sg + 1;
    {
        float q[6], r[6];
#pragma unroll
        for (int k = 0; k < 6; k++) { q[k] = x[k]*x[k]; r[k] = y[k]*y[k]; }
        float rxy =        st.wc[0] * (x[0] * y[0]);
        rxy = fmaf(st.wc[1], x[1] * y[1], rxy);
        rxy = fmaf(st.wc[2], x[2] * y[2], rxy);
        rxy = fmaf(st.wc[3], x[3] * y[3], rxy);
        rxy = fmaf(st.wc[4], x[4] * y[4], rxy);
        st.accXY = fmaf(t0 ? WAB : 1.0f, rxy, st.accXY);
#pragma unroll
        for (int k = 0; k < 4; k++) {
            float hx  = fmaf(WA, x[k], fmaf(WB, x[k+1], WA * x[k+2]));
            float hy  = fmaf(WA, y[k], fmaf(WB, y[k+1], WA * y[k+2]));
            float hxx = fmaf(WA, q[k], fmaf(WB, q[k+1], WA * q[k+2]));
            float hyy = fmaf(WA, r[k], fmaf(WB, r[k+1], WA * r[k+2]));
            st.Vpx[k]  = fmaf(WB, hx,  st.Vqx[k]);   st.Vqx[k]  = WA * hx;
            st.Vpy[k]  = fmaf(WB, hy,  st.Vqy[k]);   st.Vqy[k]  = WA * hy;
            st.Vpxx[k] = fmaf(WB, hxx, st.Vqxx[k]);  st.Vqxx[k] = WA * hxx;
            st.Vpyy[k] = fmaf(WB, hyy, st.Vqyy[k]);  st.Vqyy[k] = WA * hyy;
        }
    }

    // ---- main loop: rows r0+1 .. rend-2, xy row weight 1 (constant)
    for (int i = r0 + 1; i <= rend - 2; ++i) {
        fetch(sg, x, y);
        issue(min(nrow, 507), nsg);
        ++nrow; nsg = (nsg + 1 == NS) ? 0 : nsg + 1; sg = (sg + 1 == NS) ? 0 : sg + 1;
        vstep(x, y, st, 1.0f);
    }
    // ---- peeled tails: rows rend-1, rend (xy rim rows owned by last strip)
    fetch(sg, x, y);
    issue(min(nrow, 507), nsg);   // keeps invariant for the final fetch
    sg = (sg + 1 == NS) ? 0 : sg + 1;
    vstep(x, y, st, tl ? WAB : 0.0f);        // row rend-1 (506 if tl)
    fetch(sg, x, y);
    vstep(x, y, st, tl ? WA : 0.0f);         // row rend   (507 if tl)
    asm volatile("cp.async.wait_group 0;" ::: "memory");  // drain before exit
    __syncthreads();

    // apply output-col masks once, combine, reduce
    float accP = 0.0f;
#pragma unroll
    for (int k = 0; k < 4; k++) {
        float mk = (j0 + k <= 506) ? 1.0f : 0.0f;
        accP = fmaf(mk, st.accC[k], accP);
    }
    float acs = accP - 2.0f * st.accXY;
#pragma unroll
    for (int o = 16; o > 0; o >>= 1) acs += __shfl_xor_sync(FULLMASK, acs, o);

    if (lane == 0) sp[wid] = acs;
    __syncthreads();
    if (tid == 0) {
        g_part[blk] = (sp[0] + sp[1]) + (sp[2] + sp[3]);
        __threadfence();
        unsigned r = atomicAdd(&g_cnt, 1u);
        is_last = (r == gridDim.x - 1);
    }
    __syncthreads();
    if (is_last) {
        __threadfence();
        double ds = 0.0;
#pragma unroll
        for (int i = tid; i < 1024; i += 128) ds += (double)g_part[i];
        sh[tid] = ds;
        __syncthreads();
        for (int o = 64; o > 0; o >>= 1) {
            if (tid < o) sh[tid] += sh[tid + o];
            __syncthreads();
        }
        if (tid == 0) {
            out[0] = (float)(sh[0] * (1.0 / 252004.0));
            g_cnt = 0;   // reset for next graph replay (deterministic)
        }
    }
}

extern "C" void kernel_launch(void* const* d_in, const int* in_sizes, int n_in,
                              void* d_out, int out_size) {
    const float* X = (const float*)d_in[0];
    const float* Y = (const float*)d_in[1];
    float* out = (float*)d_out;

    // 1024 blocks = 64 images x 16 row-strips(32); 4 warps = 4 col-stripes(128)
    loss_kernel<<<1024, 128>>>(X, Y, out);
}